// round 7
// baseline (speedup 1.0000x reference)
#include <cuda_runtime.h>
#include <cuda_fp16.h>
#include <cstdint>

#define VOCAB 100000
#define EMB   128
#define NTILES (VOCAB / 32)     // 3125
#define GRID  1184              // 148 SMs * 8 blocks — all resident by construction
#define TOK_PER_WARP 8

// Scratch: vocab-major, bias-fused, L2-normalized table in FP16 (25.6 MB).
__device__ __half g_table[(size_t)VOCAB * EMB];

// Self-resetting grid barrier state (zeroed at load; last departer re-zeros).
__device__ unsigned g_arrive = 0;
__device__ unsigned g_depart = 0;

__global__ __launch_bounds__(256, 8) void fused_kernel(
        const int* __restrict__ x,
        const float* __restrict__ W,
        const float* __restrict__ b,
        float* __restrict__ out,
        int n_tok) {
    __shared__ float tile[EMB][33];   // [j][v_local], pad -> conflict-free

    const int tid  = threadIdx.x;
    const int lane = tid & 31;
    const int wid  = tid >> 5;        // 0..7

    // ======================= PHASE 1: build table =======================
    // Grid-stride over 32-vocab tiles: table[v][:] = (half) normalize(W[:,v]+b)
    for (int t = blockIdx.x; t < NTILES; t += GRID) {
        const int v0 = t * 32;

        #pragma unroll
        for (int k = 0; k < 16; k++) {
            int j = k * 8 + wid;
            tile[j][lane] = W[(size_t)j * VOCAB + v0 + lane] + b[j];
        }
        __syncthreads();

        #pragma unroll
        for (int r = 0; r < 4; r++) {
            const int v = wid * 4 + r;
            float s = 0.f;
            #pragma unroll
            for (int k = 0; k < 4; k++) {
                float e = tile[lane + 32 * k][v];
                s += e * e;
            }
            #pragma unroll
            for (int o = 16; o > 0; o >>= 1)
                s += __shfl_xor_sync(0xFFFFFFFFu, s, o);

            const float inv = 1.0f / fmaxf(sqrtf(s), 1e-12f);

            __half2* dst = reinterpret_cast<__half2*>(g_table + (size_t)(v0 + v) * EMB);
            dst[lane]      = __floats2half2_rn(tile[2 * lane][v] * inv,
                                               tile[2 * lane + 1][v] * inv);
            dst[lane + 32] = __floats2half2_rn(tile[64 + 2 * lane][v] * inv,
                                               tile[64 + 2 * lane + 1][v] * inv);
        }
        __syncthreads();   // smem reuse guard for next tile
    }

    // ======================= grid barrier (arrive) ======================
    __syncthreads();
    if (tid == 0) {
        __threadfence();                       // release: table stores visible
        atomicAdd(&g_arrive, 1u);
        while (*(volatile unsigned*)&g_arrive < (unsigned)GRID)
            __nanosleep(128);
    }
    __syncthreads();
    __threadfence();                           // acquire: see all table stores

    // ======================= PHASE 2: gather ============================
    const int gwarp       = blockIdx.x * 8 + wid;
    const int warps_total = GRID * 8;
    const int n_chunks    = (n_tok + TOK_PER_WARP - 1) / TOK_PER_WARP;

    for (int c = gwarp; c < n_chunks; c += warps_total) {
        const int t0 = c * TOK_PER_WARP;

        if (t0 + TOK_PER_WARP <= n_tok) {
            int idx[TOK_PER_WARP];
            #pragma unroll
            for (int r = 0; r < TOK_PER_WARP; r++)
                idx[r] = __ldg(&x[t0 + r]);

            // two groups of 4: MLP=4 loads in flight, lower reg pressure
            #pragma unroll
            for (int g = 0; g < 2; g++) {
                uint2 h[4];
                #pragma unroll
                for (int r = 0; r < 4; r++)
                    h[r] = __ldg(reinterpret_cast<const uint2*>(
                               g_table + (size_t)idx[g * 4 + r] * EMB) + lane);
                #pragma unroll
                for (int r = 0; r < 4; r++) {
                    float2 f0 = __half22float2(*reinterpret_cast<__half2*>(&h[r].x));
                    float2 f1 = __half22float2(*reinterpret_cast<__half2*>(&h[r].y));
                    float4 o;
                    o.x = f0.x; o.y = f0.y; o.z = f1.x; o.w = f1.y;
                    __stcs(reinterpret_cast<float4*>(
                               out + (size_t)(t0 + g * 4 + r) * EMB) + lane, o);
                }
            }
        } else {
            for (int t = t0; t < n_tok; t++) {
                uint2 h = __ldg(reinterpret_cast<const uint2*>(
                              g_table + (size_t)__ldg(&x[t]) * EMB) + lane);
                float2 f0 = __half22float2(*reinterpret_cast<__half2*>(&h.x));
                float2 f1 = __half22float2(*reinterpret_cast<__half2*>(&h.y));
                float4 o;
                o.x = f0.x; o.y = f0.y; o.z = f1.x; o.w = f1.y;
                __stcs(reinterpret_cast<float4*>(out + (size_t)t * EMB) + lane, o);
            }
        }
    }

    // ================= grid barrier (depart + self-reset) ===============
    __syncthreads();
    if (tid == 0) {
        unsigned old = atomicAdd(&g_depart, 1u);
        if (old == (unsigned)GRID - 1u) {      // last block out resets for next replay
            g_arrive = 0u;
            g_depart = 0u;
            __threadfence();
        }
    }
}

// ---------------------------------------------------------------------------
extern "C" void kernel_launch(void* const* d_in, const int* in_sizes, int n_in,
                              void* d_out, int out_size) {
    const int*   x = (const int*)d_in[0];    // [4096, 200] int32
    const float* W = (const float*)d_in[1];  // [128, 100000] fp32
    const float* b = (const float*)d_in[2];  // [128] fp32
    float* out = (float*)d_out;              // [4096, 200, 128] fp32

    const int n_tok = in_sizes[0];           // 819200

    fused_kernel<<<GRID, 256>>>(x, W, b, out, n_tok);
}

// round 9
// speedup vs baseline: 1.6231x; 1.6231x over previous
#include <cuda_runtime.h>
#include <cuda_fp16.h>
#include <cstdint>

#define VOCAB 100000
#define EMB   128

// Scratch: vocab-major, bias-fused, L2-normalized table in FP16.
// 100000 * 128 * 2B = 25.6 MB — firmly resident in GB300's ~126 MB L2.
__device__ __half g_table[(size_t)VOCAB * EMB];

// ---------------------------------------------------------------------------
// Kernel 1: table[v][:] = (half) normalize(W[:, v] + b)
// One block per 32 vocab entries. Block = 256 threads. (R3-proven, at its
// traffic floor: 51 MB read + 26 MB write ~= 13 us.)
// ---------------------------------------------------------------------------
__global__ __launch_bounds__(256) void build_table_kernel(
        const float* __restrict__ W,
        const float* __restrict__ b) {
    __shared__ float tile[EMB][33];   // [j][v_local], pad -> conflict-free reduce

    const int v0   = blockIdx.x * 32;
    const int tid  = threadIdx.x;
    const int lane = tid & 31;
    const int wid  = tid >> 5;        // 0..7

    // Load + bias: warp reads one j-row of 32 consecutive vocab cols (128B line).
    #pragma unroll
    for (int k = 0; k < 16; k++) {
        int j = k * 8 + wid;
        tile[j][lane] = W[(size_t)j * VOCAB + v0 + lane] + b[j];
    }
    __syncthreads();

    // Each warp normalizes 4 vocab rows and writes them as half2.
    #pragma unroll
    for (int r = 0; r < 4; r++) {
        const int v = wid * 4 + r;

        float s = 0.f;
        #pragma unroll
        for (int k = 0; k < 4; k++) {
            float e = tile[lane + 32 * k][v];
            s += e * e;
        }
        #pragma unroll
        for (int o = 16; o > 0; o >>= 1)
            s += __shfl_xor_sync(0xFFFFFFFFu, s, o);

        const float inv = 1.0f / fmaxf(sqrtf(s), 1e-12f);

        __half2* dst = reinterpret_cast<__half2*>(g_table + (size_t)(v0 + v) * EMB);
        dst[lane]      = __floats2half2_rn(tile[2 * lane][v] * inv,
                                           tile[2 * lane + 1][v] * inv);
        dst[lane + 32] = __floats2half2_rn(tile[64 + 2 * lane][v] * inv,
                                           tile[64 + 2 * lane + 1][v] * inv);
    }
}

// ---------------------------------------------------------------------------
// Kernel 2: gather-copy + fp16->fp32 widen. Warp handles 16 tokens: 16 index
// loads front-batched, then two groups of (8 table loads -> 8 output stores).
// Lane l moves 4 halves of each row (256B coalesced read / 512B coalesced
// write per token). Output stores use evict-first (.cs) so the 419 MB stream
// doesn't evict the table from L2.
// ---------------------------------------------------------------------------
#define TOK_PER_WARP 16

__global__ __launch_bounds__(256) void gather_kernel(
        const int* __restrict__ x,
        float* __restrict__ out,
        int n_tok) {
    const int gwarp = (blockIdx.x * blockDim.x + threadIdx.x) >> 5;
    const int lane  = threadIdx.x & 31;
    const int t0    = gwarp * TOK_PER_WARP;
    if (t0 >= n_tok) return;

    if (t0 + TOK_PER_WARP <= n_tok) {
        int idx[TOK_PER_WARP];
        #pragma unroll
        for (int r = 0; r < TOK_PER_WARP; r++)
            idx[r] = __ldg(&x[t0 + r]);

        #pragma unroll
        for (int g = 0; g < TOK_PER_WARP / 8; g++) {
            uint2 h[8];
            #pragma unroll
            for (int r = 0; r < 8; r++)
                h[r] = __ldg(reinterpret_cast<const uint2*>(
                           g_table + (size_t)idx[g * 8 + r] * EMB) + lane);

            #pragma unroll
            for (int r = 0; r < 8; r++) {
                float2 f0 = __half22float2(*reinterpret_cast<__half2*>(&h[r].x));
                float2 f1 = __half22float2(*reinterpret_cast<__half2*>(&h[r].y));
                float4 o;
                o.x = f0.x; o.y = f0.y; o.z = f1.x; o.w = f1.y;
                __stcs(reinterpret_cast<float4*>(
                           out + (size_t)(t0 + g * 8 + r) * EMB) + lane, o);
            }
        }
    } else {
        for (int t = t0; t < n_tok; t++) {
            uint2 h = __ldg(reinterpret_cast<const uint2*>(
                          g_table + (size_t)__ldg(&x[t]) * EMB) + lane);
            float2 f0 = __half22float2(*reinterpret_cast<__half2*>(&h.x));
            float2 f1 = __half22float2(*reinterpret_cast<__half2*>(&h.y));
            float4 o;
            o.x = f0.x; o.y = f0.y; o.z = f1.x; o.w = f1.y;
            __stcs(reinterpret_cast<float4*>(out + (size_t)t * EMB) + lane, o);
        }
    }
}

// ---------------------------------------------------------------------------
extern "C" void kernel_launch(void* const* d_in, const int* in_sizes, int n_in,
                              void* d_out, int out_size) {
    const int*   x = (const int*)d_in[0];    // [4096, 200] int32
    const float* W = (const float*)d_in[1];  // [128, 100000] fp32
    const float* b = (const float*)d_in[2];  // [128] fp32
    float* out = (float*)d_out;              // [4096, 200, 128] fp32

    const int n_tok = in_sizes[0];           // 819200

    build_table_kernel<<<VOCAB / 32, 256>>>(W, b);

    const int warps_needed = (n_tok + TOK_PER_WARP - 1) / TOK_PER_WARP;  // 51200
    const int blocks = (warps_needed + 7) / 8;                            // 6400
    gather_kernel<<<blocks, 256>>>(x, out, n_tok);
}